// round 1
// baseline (speedup 1.0000x reference)
#include <cuda_runtime.h>
#include <cstdint>

// Problem constants
#define NROWS 32768
#define DDIM  512
#define CB    16     // codebooks
#define KC    16     // codewords per codebook
#define SV    32     // subvector length
#define MOUT  1024

// ---- device scratch (no allocations allowed) ----
__device__ float          g_pn[CB * KC];            // ||proto||^2
__device__ float          g_bsums[2048];            // per-block X sums
__device__ float          g_scale;                  // mean(X)
__device__ unsigned char  g_codes[NROWS * CB];      // PQ codes

// ============================================================
// Kernel 0: prototype squared norms. 1 block x 256 threads.
// ============================================================
__global__ void prep_pnorm(const float* __restrict__ protos) {
    int t = threadIdx.x;                 // t = c*16 + k
    const float* p = protos + t * SV;
    float s = 0.f;
#pragma unroll
    for (int i = 0; i < SV; i++) s += p[i] * p[i];
    g_pn[t] = s;
}

// ============================================================
// Kernel 1: encode. Block = 256 threads, 16 rows per block.
// Thread tile: 4 rows x 4 codewords for one codebook.
// smem: Xs padded (stride 33 per subvec, 528 per row) to kill
// bank conflicts; Pt transposed [c][s][k] with stride 515.
// Also accumulates the block's partial sum of X for mean(X).
// ============================================================
#define ENC_SMEM ((16*528 + 16*515) * 4)

__global__ void encode_kernel(const float* __restrict__ X,
                              const float* __restrict__ protos) {
    extern __shared__ float sm[];
    float* Xs = sm;                 // 16 rows * 528
    float* Pt = sm + 16 * 528;      // 16 cb * 515

    const int tid  = threadIdx.x;
    const int row0 = blockIdx.x * 16;

    // --- stage X tile (coalesced) + local sum for mean ---
    float lsum = 0.f;
#pragma unroll
    for (int it = 0; it < 32; it++) {
        int i = tid + it * 256;          // i in [0, 8192)
        int r = i >> 9, d = i & 511;
        float v = X[(row0 + r) * DDIM + d];
        lsum += v;
        Xs[r * 528 + (d >> 5) * 33 + (d & 31)] = v;
    }
    // --- stage protos transposed ---
#pragma unroll
    for (int it = 0; it < 32; it++) {
        int i = tid + it * 256;          // i in [0, 8192)
        int c = i >> 9, k = (i >> 5) & 15, s = i & 31;
        Pt[c * 515 + s * 16 + k] = protos[i];
    }
    __syncthreads();

    // --- main dot products ---
    const int kg = tid & 3;              // codeword group (4 ks)
    const int c  = (tid >> 2) & 15;      // codebook
    const int rg = tid >> 6;             // row group (4 rows)

    float pnl[4];
#pragma unroll
    for (int kk = 0; kk < 4; kk++) pnl[kk] = g_pn[c * 16 + kg * 4 + kk];

    float acc[4][4];
#pragma unroll
    for (int r = 0; r < 4; r++)
#pragma unroll
        for (int kk = 0; kk < 4; kk++) acc[r][kk] = 0.f;

    const float* xb = Xs + (rg * 4) * 528 + c * 33;
    const float* pb = Pt + c * 515 + kg * 4;

#pragma unroll 8
    for (int s = 0; s < 32; s++) {
        float xv[4], pv[4];
#pragma unroll
        for (int r = 0; r < 4; r++) xv[r] = xb[r * 528 + s];
#pragma unroll
        for (int kk = 0; kk < 4; kk++) pv[kk] = pb[s * 16 + kk];
#pragma unroll
        for (int r = 0; r < 4; r++)
#pragma unroll
            for (int kk = 0; kk < 4; kk++)
                acc[r][kk] = fmaf(xv[r], pv[kk], acc[r][kk]);
    }

    // --- argmin per (row, codebook): local then across 4 kg lanes ---
#pragma unroll
    for (int r = 0; r < 4; r++) {
        float bd = pnl[0] - 2.f * acc[r][0];
        int   bk = kg * 4;
#pragma unroll
        for (int kk = 1; kk < 4; kk++) {
            float dd = pnl[kk] - 2.f * acc[r][kk];
            if (dd < bd) { bd = dd; bk = kg * 4 + kk; }
        }
#pragma unroll
        for (int off = 1; off < 4; off <<= 1) {
            float od = __shfl_xor_sync(0xffffffffu, bd, off);
            int   ok = __shfl_xor_sync(0xffffffffu, bk, off);
            if (od < bd || (od == bd && ok < bk)) { bd = od; bk = ok; }
        }
        if (kg == 0)
            g_codes[(row0 + rg * 4 + r) * CB + c] = (unsigned char)bk;
    }

    // --- deterministic block reduction of lsum ---
    __shared__ float red[8];
#pragma unroll
    for (int off = 16; off; off >>= 1)
        lsum += __shfl_xor_sync(0xffffffffu, lsum, off);
    if ((tid & 31) == 0) red[tid >> 5] = lsum;
    __syncthreads();
    if (tid < 8) {
        float v = red[tid];
        v += __shfl_xor_sync(0xffu, v, 1);
        v += __shfl_xor_sync(0xffu, v, 2);
        v += __shfl_xor_sync(0xffu, v, 4);
        if (tid == 0) g_bsums[blockIdx.x] = v;
    }
}

// ============================================================
// Kernel 2: reduce block sums -> g_scale = mean(X). 1 block.
// ============================================================
__global__ void reduce_kernel() {
    const int tid = threadIdx.x;         // 256 threads
    float s = 0.f;
    for (int i = tid; i < 2048; i += 256) s += g_bsums[i];
    __shared__ float red[8];
#pragma unroll
    for (int off = 16; off; off >>= 1)
        s += __shfl_xor_sync(0xffffffffu, s, off);
    if ((tid & 31) == 0) red[tid >> 5] = s;
    __syncthreads();
    if (tid < 8) {
        float v = red[tid];
        v += __shfl_xor_sync(0xffu, v, 1);
        v += __shfl_xor_sync(0xffu, v, 2);
        v += __shfl_xor_sync(0xffu, v, 4);
        if (tid == 0) g_scale = v * (1.0f / (float)(NROWS * DDIM));
    }
}

// ============================================================
// Kernel 3: paired-LUT accumulate.
// Grid (64 m-tiles of 16 cols, 16 row chunks of 2048 rows).
// smem: stage = luts[:, :, m0:m0+16] (16KB), then
//       plut[8][256][16+pad4] = pairwise-fused LUT (160KB).
// Each thread: one float4 column group, loops 32 rows.
// 8 LDS.128 + 32 FADD per output float4 (vs 16 unpaired).
// ============================================================
#define ACC_SMEM ((4096 + 8 * 256 * 20) * 4)

__global__ void accum_kernel(const float* __restrict__ luts,
                             float* __restrict__ out) {
    extern __shared__ float sm[];
    float4* stage4 = (float4*)sm;        // 1024 float4 = 4096 floats
    float*  plut   = sm + 4096;          // 8*256*20 floats

    const int tid = threadIdx.x;
    const int m0  = blockIdx.x * 16;

    // --- stage lut slice [16c][16k][16m] as float4 ---
#pragma unroll
    for (int it = 0; it < 4; it++) {
        int i = tid + it * 256;          // i < 1024
        int rowck = i >> 2, j4 = i & 3;
        stage4[i] = *(const float4*)(luts + rowck * MOUT + m0 + j4 * 4);
    }
    __syncthreads();

    // --- build pairwise LUT (vectorized) ---
#pragma unroll
    for (int it = 0; it < 32; it++) {
        int i   = tid + it * 256;        // i < 8192
        int j4  = i & 3;
        int k12 = (i >> 2) & 255;
        int p   = i >> 10;
        int k1  = k12 >> 4, k2 = k12 & 15;
        float4 a = stage4[((2 * p) * 16 + k1) * 4 + j4];
        float4 b = stage4[((2 * p + 1) * 16 + k2) * 4 + j4];
        float4 v;
        v.x = a.x + b.x; v.y = a.y + b.y; v.z = a.z + b.z; v.w = a.w + b.w;
        *(float4*)(plut + (p * 256 + k12) * 20 + j4 * 4) = v;
    }
    __syncthreads();

    const float scale = g_scale;
    const int mg = tid & 3;              // which float4 of the 16-col tile
    const int rl = tid >> 2;             // 64 rows in flight
    const int rowBase = blockIdx.y * 2048;

    for (int rr = 0; rr < 32; rr++) {
        const int row = rowBase + rl + rr * 64;
        const uint4 cw = *(const uint4*)(g_codes + row * CB);
        const uint32_t w[4] = {cw.x, cw.y, cw.z, cw.w};

        float4 acc = make_float4(0.f, 0.f, 0.f, 0.f);
#pragma unroll
        for (int p = 0; p < 8; p++) {
            uint32_t ww = w[p >> 1];
            uint32_t sh = (p & 1) * 16;
            int pk = (int)(((ww >> sh) & 0xFFu) * 16u + ((ww >> (sh + 8)) & 0xFFu));
            const float4 v = *(const float4*)(plut + (p * 256 + pk) * 20 + mg * 4);
            acc.x += v.x; acc.y += v.y; acc.z += v.z; acc.w += v.w;
        }
        float4 o;
        o.x = acc.x * scale; o.y = acc.y * scale;
        o.z = acc.z * scale; o.w = acc.w * scale;
        *(float4*)(out + (size_t)row * MOUT + m0 + mg * 4) = o;
    }
}

// ============================================================
extern "C" void kernel_launch(void* const* d_in, const int* in_sizes, int n_in,
                              void* d_out, int out_size) {
    const float* X      = (const float*)d_in[0];   // [32768, 512]
    const float* protos = (const float*)d_in[1];   // [16, 16, 32]
    const float* luts   = (const float*)d_in[2];   // [16, 16, 1024]
    float* out = (float*)d_out;                    // [32768, 1024]

    cudaFuncSetAttribute(encode_kernel,
        cudaFuncAttributeMaxDynamicSharedMemorySize, ENC_SMEM);
    cudaFuncSetAttribute(accum_kernel,
        cudaFuncAttributeMaxDynamicSharedMemorySize, ACC_SMEM);

    prep_pnorm<<<1, 256>>>(protos);
    encode_kernel<<<NROWS / 16, 256, ENC_SMEM>>>(X, protos);
    reduce_kernel<<<1, 256>>>();
    accum_kernel<<<dim3(64, 16), 256, ACC_SMEM>>>(luts, out);
}

// round 3
// speedup vs baseline: 1.6419x; 1.6419x over previous
#include <cuda_runtime.h>
#include <cstdint>

// Problem constants
#define NROWS 32768
#define DDIM  512
#define CB    16     // codebooks
#define KC    16     // codewords per codebook
#define SV    32     // subvector length
#define MOUT  1024

// ---- device scratch (no allocations allowed) ----
__device__ float          g_pn[CB * KC];            // ||proto||^2
__device__ float          g_bsums[1024];            // per-block X sums
__device__ float          g_scale;                  // mean(X)
__device__ unsigned char  g_codes[NROWS * CB];      // PQ codes

// ============================================================
// Kernel 0: prototype squared norms. 1 block x 256 threads.
// ============================================================
__global__ void prep_pnorm(const float* __restrict__ protos) {
    int t = threadIdx.x;                 // t = c*16 + k
    const float* p = protos + t * SV;
    float s = 0.f;
#pragma unroll
    for (int i = 0; i < SV; i++) s += p[i] * p[i];
    g_pn[t] = s;
}

// ============================================================
// Kernel 1: encode. Block = 512 threads, 32 rows per block.
// Thread tile: 4 rows x 4 codewords for one codebook.
// smem layouts (all float4-read, phase-conflict-free):
//   Xs[c][s][r] : addr = c*1156 + s*36 + r      (r = row in block, 0..31)
//   Pt[s][c][k] : addr = s*260  + c*16 + k
// Inner loop: 2 LDS.128 + 16 FFMA per (s) step -> FMA-bound.
// Also accumulates the block's partial sum of X for mean(X).
// ============================================================
#define XCPAD 1156
#define XSPAD 36
#define PTPAD 260
#define ENC_SMEM ((16 * XCPAD + 32 * PTPAD) * 4)

__global__ void encode_kernel(const float* __restrict__ X,
                              const float* __restrict__ protos) {
    extern __shared__ float sm[];
    float* Xs = sm;                  // 16 * 1156
    float* Pt = sm + 16 * XCPAD;     // 32 * 260

    const int tid  = threadIdx.x;    // 512
    const int row0 = blockIdx.x * 32;

    // --- stage X tile: 4096 float4-slots (4 rows each), coalesced LDG ---
    float lsum = 0.f;
#pragma unroll
    for (int it = 0; it < 8; it++) {
        int slot = tid + it * 512;       // < 4096
        int d  = slot & 511;
        int r4 = slot >> 9;              // row group 0..7
        int c  = d >> 5, s = d & 31;
        const float* xp = X + (size_t)(row0 + r4 * 4) * DDIM + d;
        float v0 = xp[0];
        float v1 = xp[DDIM];
        float v2 = xp[2 * DDIM];
        float v3 = xp[3 * DDIM];
        lsum += (v0 + v1) + (v2 + v3);
        *(float4*)(Xs + c * XCPAD + s * XSPAD + r4 * 4) =
            make_float4(v0, v1, v2, v3);
    }
    // --- stage protos transposed [s][c][k] ---
#pragma unroll
    for (int it = 0; it < 16; it++) {
        int i = tid + it * 512;          // < 8192
        int c = i >> 9, k = (i >> 5) & 15, s = i & 31;
        Pt[s * PTPAD + c * 16 + k] = protos[i];
    }
    __syncthreads();

    // --- main dot products: thread = (kg, c, rg) -> 4 rows x 4 ks ---
    const int kg = tid & 3;              // codeword group (4 ks)
    const int c  = (tid >> 2) & 15;      // codebook
    const int rg = tid >> 6;             // row group 0..7

    float pnl[4];
#pragma unroll
    for (int kk = 0; kk < 4; kk++) pnl[kk] = g_pn[c * 16 + kg * 4 + kk];

    float acc[4][4];
#pragma unroll
    for (int r = 0; r < 4; r++)
#pragma unroll
        for (int kk = 0; kk < 4; kk++) acc[r][kk] = 0.f;

    const float* xb = Xs + c * XCPAD + rg * 4;
    const float* pb = Pt + c * 16 + kg * 4;

#pragma unroll
    for (int s = 0; s < 32; s++) {
        const float4 xv = *(const float4*)(xb + s * XSPAD);
        const float4 pv = *(const float4*)(pb + s * PTPAD);
        acc[0][0] = fmaf(xv.x, pv.x, acc[0][0]);
        acc[0][1] = fmaf(xv.x, pv.y, acc[0][1]);
        acc[0][2] = fmaf(xv.x, pv.z, acc[0][2]);
        acc[0][3] = fmaf(xv.x, pv.w, acc[0][3]);
        acc[1][0] = fmaf(xv.y, pv.x, acc[1][0]);
        acc[1][1] = fmaf(xv.y, pv.y, acc[1][1]);
        acc[1][2] = fmaf(xv.y, pv.z, acc[1][2]);
        acc[1][3] = fmaf(xv.y, pv.w, acc[1][3]);
        acc[2][0] = fmaf(xv.z, pv.x, acc[2][0]);
        acc[2][1] = fmaf(xv.z, pv.y, acc[2][1]);
        acc[2][2] = fmaf(xv.z, pv.z, acc[2][2]);
        acc[2][3] = fmaf(xv.z, pv.w, acc[2][3]);
        acc[3][0] = fmaf(xv.w, pv.x, acc[3][0]);
        acc[3][1] = fmaf(xv.w, pv.y, acc[3][1]);
        acc[3][2] = fmaf(xv.w, pv.z, acc[3][2]);
        acc[3][3] = fmaf(xv.w, pv.w, acc[3][3]);
    }

    // --- argmin per (row, codebook): local then across 4 kg lanes ---
#pragma unroll
    for (int r = 0; r < 4; r++) {
        float bd = pnl[0] - 2.f * acc[r][0];
        int   bk = kg * 4;
#pragma unroll
        for (int kk = 1; kk < 4; kk++) {
            float dd = pnl[kk] - 2.f * acc[r][kk];
            if (dd < bd) { bd = dd; bk = kg * 4 + kk; }
        }
#pragma unroll
        for (int off = 1; off < 4; off <<= 1) {
            float od = __shfl_xor_sync(0xffffffffu, bd, off);
            int   ok = __shfl_xor_sync(0xffffffffu, bk, off);
            if (od < bd || (od == bd && ok < bk)) { bd = od; bk = ok; }
        }
        if (kg == 0)
            g_codes[(row0 + rg * 4 + r) * CB + c] = (unsigned char)bk;
    }

    // --- deterministic block reduction of lsum (512 thr = 16 warps) ---
    __shared__ float red[16];
#pragma unroll
    for (int off = 16; off; off >>= 1)
        lsum += __shfl_xor_sync(0xffffffffu, lsum, off);
    if ((tid & 31) == 0) red[tid >> 5] = lsum;
    __syncthreads();
    if (tid < 16) {
        float v = red[tid];
        v += __shfl_xor_sync(0xffffu, v, 1);
        v += __shfl_xor_sync(0xffffu, v, 2);
        v += __shfl_xor_sync(0xffffu, v, 4);
        v += __shfl_xor_sync(0xffffu, v, 8);
        if (tid == 0) g_bsums[blockIdx.x] = v;
    }
}

// ============================================================
// Kernel 2: reduce block sums -> g_scale = mean(X). 1 block.
// ============================================================
__global__ void reduce_kernel() {
    const int tid = threadIdx.x;         // 256 threads
    float s = 0.f;
    for (int i = tid; i < 1024; i += 256) s += g_bsums[i];
    __shared__ float red[8];
#pragma unroll
    for (int off = 16; off; off >>= 1)
        s += __shfl_xor_sync(0xffffffffu, s, off);
    if ((tid & 31) == 0) red[tid >> 5] = s;
    __syncthreads();
    if (tid < 8) {
        float v = red[tid];
        v += __shfl_xor_sync(0xffu, v, 1);
        v += __shfl_xor_sync(0xffu, v, 2);
        v += __shfl_xor_sync(0xffu, v, 4);
        if (tid == 0) g_scale = v * (1.0f / (float)(NROWS * DDIM));
    }
}

// ============================================================
// Kernel 3: paired-LUT accumulate. 1024 threads/block.
// Grid (64 m-tiles of 16 cols, 16 row chunks of 2048 rows).
// smem: stage = luts[:, :, m0:m0+16] (16KB), then
//       plut[8][256][16] pairwise-fused LUT (128KB, stride 16
//       -> avg phase conflict 1.5x instead of 1.875x at pad-20).
// 8 LDS.128 + 32 FADD per output float4.
// ============================================================
#define ACC_SMEM ((4096 + 8 * 256 * 16) * 4)

__global__ void accum_kernel(const float* __restrict__ luts,
                             float* __restrict__ out) {
    extern __shared__ float sm[];
    float4* stage4 = (float4*)sm;        // 1024 float4 = 4096 floats
    float*  plut   = sm + 4096;          // 8*256*16 floats

    const int tid = threadIdx.x;         // 1024
    const int m0  = blockIdx.x * 16;

    // --- stage lut slice [16c][16k][16m] as float4 (1 iter) ---
    {
        int rowck = tid >> 2, j4 = tid & 3;
        stage4[tid] = *(const float4*)(luts + rowck * MOUT + m0 + j4 * 4);
    }
    __syncthreads();

    // --- build pairwise LUT (fully contiguous stores) ---
#pragma unroll
    for (int it = 0; it < 8; it++) {
        int i   = tid + it * 1024;       // < 8192
        int j4  = i & 3;
        int k12 = (i >> 2) & 255;
        int p   = i >> 10;
        int k1  = k12 >> 4, k2 = k12 & 15;
        float4 a = stage4[((2 * p) * 16 + k1) * 4 + j4];
        float4 b = stage4[((2 * p + 1) * 16 + k2) * 4 + j4];
        float4 v;
        v.x = a.x + b.x; v.y = a.y + b.y; v.z = a.z + b.z; v.w = a.w + b.w;
        *(float4*)(plut + (i << 2)) = v;   // ((p*256+k12)*16 + j4*4)
    }
    __syncthreads();

    const float scale = g_scale;
    const int mg = tid & 3;              // which float4 of the 16-col tile
    const int rl = tid >> 2;             // 256 rows in flight
    const int rowBase = blockIdx.y * 2048;

#pragma unroll
    for (int rr = 0; rr < 8; rr++) {
        const int row = rowBase + rl + rr * 256;
        const uint4 cw = *(const uint4*)(g_codes + row * CB);
        const uint32_t w[4] = {cw.x, cw.y, cw.z, cw.w};

        float4 acc = make_float4(0.f, 0.f, 0.f, 0.f);
#pragma unroll
        for (int p = 0; p < 8; p++) {
            uint32_t ww = w[p >> 1];
            uint32_t sh = (p & 1) * 16;
            int pk = (int)(((ww >> sh) & 0xFFu) * 16u + ((ww >> (sh + 8)) & 0xFFu));
            const float4 v = *(const float4*)(plut + ((p * 256 + pk) << 4) + (mg << 2));
            acc.x += v.x; acc.y += v.y; acc.z += v.z; acc.w += v.w;
        }
        float4 o;
        o.x = acc.x * scale; o.y = acc.y * scale;
        o.z = acc.z * scale; o.w = acc.w * scale;
        *(float4*)(out + (size_t)row * MOUT + m0 + mg * 4) = o;
    }
}

// ============================================================
extern "C" void kernel_launch(void* const* d_in, const int* in_sizes, int n_in,
                              void* d_out, int out_size) {
    const float* X      = (const float*)d_in[0];   // [32768, 512]
    const float* protos = (const float*)d_in[1];   // [16, 16, 32]
    const float* luts   = (const float*)d_in[2];   // [16, 16, 1024]
    float* out = (float*)d_out;                    // [32768, 1024]

    cudaFuncSetAttribute(encode_kernel,
        cudaFuncAttributeMaxDynamicSharedMemorySize, ENC_SMEM);
    cudaFuncSetAttribute(accum_kernel,
        cudaFuncAttributeMaxDynamicSharedMemorySize, ACC_SMEM);

    prep_pnorm<<<1, 256>>>(protos);
    encode_kernel<<<NROWS / 32, 512, ENC_SMEM>>>(X, protos);
    reduce_kernel<<<1, 256>>>();
    accum_kernel<<<dim3(64, 16), 1024, ACC_SMEM>>>(luts, out);
}

// round 4
// speedup vs baseline: 1.8776x; 1.1435x over previous
#include <cuda_runtime.h>
#include <cuda_fp16.h>
#include <cstdint>

// Problem constants
#define NROWS 32768
#define DDIM  512
#define CB    16     // codebooks
#define KC    16     // codewords per codebook
#define SV    32     // subvector length
#define MOUT  1024

// ---- device scratch (no allocations allowed) ----
__device__ float          g_pn[CB * KC];            // ||proto||^2
__device__ float          g_bsums[1024];            // per-block X sums
__device__ float          g_scale;                  // mean(X)
__device__ unsigned char  g_codes[NROWS * CB];      // PQ codes

// ============================================================
// Kernel 0: prototype squared norms. 1 block x 256 threads.
// ============================================================
__global__ void prep_pnorm(const float* __restrict__ protos) {
    int t = threadIdx.x;                 // t = c*16 + k
    const float* p = protos + t * SV;
    float s = 0.f;
#pragma unroll
    for (int i = 0; i < SV; i++) s += p[i] * p[i];
    g_pn[t] = s;
}

// ============================================================
// Kernel 1: encode. Block = 512 threads, 32 rows per block.
// Thread tile: 4 rows x 4 codewords for one codebook.
// smem layouts (all float4-read, phase-conflict-free):
//   Xs[c][s][r] : addr = c*1156 + s*36 + r      (r = row in block, 0..31)
//   Pt[s][c][k] : addr = s*260  + c*16 + k
// Inner loop: 2 LDS.128 + 16 FFMA per (s) step -> FMA-bound.
// Also accumulates the block's partial sum of X for mean(X).
// ============================================================
#define XCPAD 1156
#define XSPAD 36
#define PTPAD 260
#define ENC_SMEM ((16 * XCPAD + 32 * PTPAD) * 4)

__global__ void encode_kernel(const float* __restrict__ X,
                              const float* __restrict__ protos) {
    extern __shared__ float sm[];
    float* Xs = sm;                  // 16 * 1156
    float* Pt = sm + 16 * XCPAD;     // 32 * 260

    const int tid  = threadIdx.x;    // 512
    const int row0 = blockIdx.x * 32;

    // --- stage X tile: 4096 float4-slots (4 rows each), coalesced LDG ---
    float lsum = 0.f;
#pragma unroll
    for (int it = 0; it < 8; it++) {
        int slot = tid + it * 512;       // < 4096
        int d  = slot & 511;
        int r4 = slot >> 9;              // row group 0..7
        int c  = d >> 5, s = d & 31;
        const float* xp = X + (size_t)(row0 + r4 * 4) * DDIM + d;
        float v0 = xp[0];
        float v1 = xp[DDIM];
        float v2 = xp[2 * DDIM];
        float v3 = xp[3 * DDIM];
        lsum += (v0 + v1) + (v2 + v3);
        *(float4*)(Xs + c * XCPAD + s * XSPAD + r4 * 4) =
            make_float4(v0, v1, v2, v3);
    }
    // --- stage protos transposed [s][c][k] ---
#pragma unroll
    for (int it = 0; it < 16; it++) {
        int i = tid + it * 512;          // < 8192
        int c = i >> 9, k = (i >> 5) & 15, s = i & 31;
        Pt[s * PTPAD + c * 16 + k] = protos[i];
    }
    __syncthreads();

    // --- main dot products: thread = (kg, c, rg) -> 4 rows x 4 ks ---
    const int kg = tid & 3;              // codeword group (4 ks)
    const int c  = (tid >> 2) & 15;      // codebook
    const int rg = tid >> 6;             // row group 0..7

    float pnl[4];
#pragma unroll
    for (int kk = 0; kk < 4; kk++) pnl[kk] = g_pn[c * 16 + kg * 4 + kk];

    float acc[4][4];
#pragma unroll
    for (int r = 0; r < 4; r++)
#pragma unroll
        for (int kk = 0; kk < 4; kk++) acc[r][kk] = 0.f;

    const float* xb = Xs + c * XCPAD + rg * 4;
    const float* pb = Pt + c * 16 + kg * 4;

#pragma unroll
    for (int s = 0; s < 32; s++) {
        const float4 xv = *(const float4*)(xb + s * XSPAD);
        const float4 pv = *(const float4*)(pb + s * PTPAD);
        acc[0][0] = fmaf(xv.x, pv.x, acc[0][0]);
        acc[0][1] = fmaf(xv.x, pv.y, acc[0][1]);
        acc[0][2] = fmaf(xv.x, pv.z, acc[0][2]);
        acc[0][3] = fmaf(xv.x, pv.w, acc[0][3]);
        acc[1][0] = fmaf(xv.y, pv.x, acc[1][0]);
        acc[1][1] = fmaf(xv.y, pv.y, acc[1][1]);
        acc[1][2] = fmaf(xv.y, pv.z, acc[1][2]);
        acc[1][3] = fmaf(xv.y, pv.w, acc[1][3]);
        acc[2][0] = fmaf(xv.z, pv.x, acc[2][0]);
        acc[2][1] = fmaf(xv.z, pv.y, acc[2][1]);
        acc[2][2] = fmaf(xv.z, pv.z, acc[2][2]);
        acc[2][3] = fmaf(xv.z, pv.w, acc[2][3]);
        acc[3][0] = fmaf(xv.w, pv.x, acc[3][0]);
        acc[3][1] = fmaf(xv.w, pv.y, acc[3][1]);
        acc[3][2] = fmaf(xv.w, pv.z, acc[3][2]);
        acc[3][3] = fmaf(xv.w, pv.w, acc[3][3]);
    }

    // --- argmin per (row, codebook): local then across 4 kg lanes ---
#pragma unroll
    for (int r = 0; r < 4; r++) {
        float bd = pnl[0] - 2.f * acc[r][0];
        int   bk = kg * 4;
#pragma unroll
        for (int kk = 1; kk < 4; kk++) {
            float dd = pnl[kk] - 2.f * acc[r][kk];
            if (dd < bd) { bd = dd; bk = kg * 4 + kk; }
        }
#pragma unroll
        for (int off = 1; off < 4; off <<= 1) {
            float od = __shfl_xor_sync(0xffffffffu, bd, off);
            int   ok = __shfl_xor_sync(0xffffffffu, bk, off);
            if (od < bd || (od == bd && ok < bk)) { bd = od; bk = ok; }
        }
        if (kg == 0)
            g_codes[(row0 + rg * 4 + r) * CB + c] = (unsigned char)bk;
    }

    // --- deterministic block reduction of lsum (512 thr = 16 warps) ---
    __shared__ float red[16];
#pragma unroll
    for (int off = 16; off; off >>= 1)
        lsum += __shfl_xor_sync(0xffffffffu, lsum, off);
    if ((tid & 31) == 0) red[tid >> 5] = lsum;
    __syncthreads();
    if (tid < 16) {
        float v = red[tid];
        v += __shfl_xor_sync(0xffffu, v, 1);
        v += __shfl_xor_sync(0xffffu, v, 2);
        v += __shfl_xor_sync(0xffffu, v, 4);
        v += __shfl_xor_sync(0xffffu, v, 8);
        if (tid == 0) g_bsums[blockIdx.x] = v;
    }
}

// ============================================================
// Kernel 2: reduce block sums -> g_scale = mean(X). 1 block.
// ============================================================
__global__ void reduce_kernel() {
    const int tid = threadIdx.x;         // 256 threads
    float s = 0.f;
    for (int i = tid; i < 1024; i += 256) s += g_bsums[i];
    __shared__ float red[8];
#pragma unroll
    for (int off = 16; off; off >>= 1)
        s += __shfl_xor_sync(0xffffffffu, s, off);
    if ((tid & 31) == 0) red[tid >> 5] = s;
    __syncthreads();
    if (tid < 8) {
        float v = red[tid];
        v += __shfl_xor_sync(0xffu, v, 1);
        v += __shfl_xor_sync(0xffu, v, 2);
        v += __shfl_xor_sync(0xffu, v, 4);
        if (tid == 0) g_scale = v * (1.0f / (float)(NROWS * DDIM));
    }
}

// ============================================================
// Kernel 3: paired-LUT accumulate, fp16 plut, 32-col m-tiles.
// Grid (32 m-tiles of 32 cols, 32 row chunks of 1024 rows),
// 1024 threads/block.
// smem: stage = luts[:, :, m0:m0+32] fp32 (32KB), then
//       plutH[8][256][32] fp16 pairwise-fused LUT (128KB).
// Per row per p: one LDS.64 per lane (8 lanes/row -> 32 cols),
// i.e. half the LDS bytes of the fp32/16-col version.
// Pairs summed in fp32, rounded once to fp16; accumulation fp32.
// ============================================================
#define ACC_SMEM (256 * 32 * 4 + 8 * 256 * 32 * 2)

__global__ void accum_kernel(const float* __restrict__ luts,
                             float* __restrict__ out) {
    extern __shared__ float sm[];
    float*   stage = sm;                         // 256 * 32 floats
    __half*  plutH = (__half*)(sm + 256 * 32);   // 8*256*32 halfs

    const int tid = threadIdx.x;         // 1024
    const int m0  = blockIdx.x * 32;

    // --- stage lut slice [16c*16k][32m] fp32 (conflict-free float4) ---
#pragma unroll
    for (int it = 0; it < 2; it++) {
        int i = tid + it * 1024;         // < 2048  (256 rows * 8 float4)
        int rowck = i >> 3, q = i & 7;
        *(float4*)(stage + rowck * 32 + q * 4) =
            *(const float4*)(luts + rowck * MOUT + m0 + q * 4);
    }
    __syncthreads();

    // --- build pairwise fp16 LUT: 8*256 entries x 32 cols ---
#pragma unroll
    for (int it = 0; it < 16; it++) {
        int i     = tid + it * 1024;     // < 16384 (entry*8 + q)
        int q     = i & 7;               // float4 group within 32 cols
        int entry = i >> 3;              // p*256 + k12
        int k12   = entry & 255;
        int p     = entry >> 8;
        int k1    = k12 >> 4, k2 = k12 & 15;
        const float4 a = *(const float4*)(stage + ((2 * p) * 16 + k1) * 32 + q * 4);
        const float4 b = *(const float4*)(stage + ((2 * p + 1) * 16 + k2) * 32 + q * 4);
        __half2 h0 = __floats2half2_rn(a.x + b.x, a.y + b.y);
        __half2 h1 = __floats2half2_rn(a.z + b.z, a.w + b.w);
        uint2 pk2;
        pk2.x = *(uint32_t*)&h0;
        pk2.y = *(uint32_t*)&h1;
        *(uint2*)(plutH + (size_t)entry * 32 + q * 4) = pk2;
    }
    __syncthreads();

    const float scale = g_scale;
    const int mg = tid & 7;              // which half4 (4 cols) of 32-col tile
    const int rl = tid >> 3;             // 128 rows in flight
    const int rowBase = blockIdx.y * 1024;

#pragma unroll
    for (int rr = 0; rr < 8; rr++) {
        const int row = rowBase + rl + rr * 128;
        const uint4 cw = *(const uint4*)(g_codes + row * CB);
        const uint32_t w[4] = {cw.x, cw.y, cw.z, cw.w};

        float a0 = 0.f, a1 = 0.f, a2 = 0.f, a3 = 0.f;
#pragma unroll
        for (int p = 0; p < 8; p++) {
            uint32_t ww = w[p >> 1];
            uint32_t sh = (p & 1) * 16;
            int pk = (int)(((ww >> sh) & 0xFFu) * 16u + ((ww >> (sh + 8)) & 0xFFu));
            const uint2 v = *(const uint2*)(plutH + (size_t)(p * 256 + pk) * 32 + mg * 4);
            const float2 f0 = __half22float2(*(const __half2*)&v.x);
            const float2 f1 = __half22float2(*(const __half2*)&v.y);
            a0 += f0.x; a1 += f0.y; a2 += f1.x; a3 += f1.y;
        }
        float4 o;
        o.x = a0 * scale; o.y = a1 * scale;
        o.z = a2 * scale; o.w = a3 * scale;
        *(float4*)(out + (size_t)row * MOUT + m0 + mg * 4) = o;
    }
}

// ============================================================
extern "C" void kernel_launch(void* const* d_in, const int* in_sizes, int n_in,
                              void* d_out, int out_size) {
    const float* X      = (const float*)d_in[0];   // [32768, 512]
    const float* protos = (const float*)d_in[1];   // [16, 16, 32]
    const float* luts   = (const float*)d_in[2];   // [16, 16, 1024]
    float* out = (float*)d_out;                    // [32768, 1024]

    cudaFuncSetAttribute(encode_kernel,
        cudaFuncAttributeMaxDynamicSharedMemorySize, ENC_SMEM);
    cudaFuncSetAttribute(accum_kernel,
        cudaFuncAttributeMaxDynamicSharedMemorySize, ACC_SMEM);

    prep_pnorm<<<1, 256>>>(protos);
    encode_kernel<<<NROWS / 32, 512, ENC_SMEM>>>(X, protos);
    reduce_kernel<<<1, 256>>>();
    accum_kernel<<<dim3(32, 32), 1024, ACC_SMEM>>>(luts, out);
}

// round 5
// speedup vs baseline: 1.9232x; 1.0243x over previous
#include <cuda_runtime.h>
#include <cuda_fp16.h>
#include <cstdint>

// Problem constants
#define NROWS 32768
#define DDIM  512
#define CB    16     // codebooks
#define KC    16     // codewords per codebook
#define SV    32     // subvector length
#define MOUT  1024

// ---- device scratch (no allocations allowed) ----
__device__ float          g_pn[CB * KC];            // ||proto||^2
__device__ float          g_bsums[1024];            // per-block X sums
__device__ float          g_scale;                  // mean(X)
__device__ unsigned short g_pcodes[NROWS * 8];      // paired codes: p*256+k1*16+k2

// ============================================================
// Kernel 0: prototype squared norms. 1 block x 256 threads.
// ============================================================
__global__ void prep_pnorm(const float* __restrict__ protos) {
    int t = threadIdx.x;                 // t = c*16 + k
    const float* p = protos + t * SV;
    float s = 0.f;
#pragma unroll
    for (int i = 0; i < SV; i++) s += p[i] * p[i];
    g_pn[t] = s;
}

// ============================================================
// Kernel 1: encode. Block = 512 threads, 32 rows per block.
// Thread tile: 4 rows x 4 codewords for one codebook.
// smem layouts (all float4-read, phase-conflict-free):
//   Xs[c][s][r] : addr = c*1156 + s*36 + r      (r = row in block, 0..31)
//   Pt[s][c][k] : addr = s*260  + c*16 + k
// Inner loop: 2 LDS.128 + 16 FFMA per (s) step -> FMA-bound.
// Emits PAIRED codes (u16 entry indices) for the accum kernel.
// Also accumulates the block's partial sum of X for mean(X).
// ============================================================
#define XCPAD 1156
#define XSPAD 36
#define PTPAD 260
#define ENC_SMEM ((16 * XCPAD + 32 * PTPAD) * 4)

__global__ void encode_kernel(const float* __restrict__ X,
                              const float* __restrict__ protos) {
    extern __shared__ float sm[];
    float* Xs = sm;                  // 16 * 1156
    float* Pt = sm + 16 * XCPAD;     // 32 * 260

    __shared__ unsigned char codes_s[32 * 16];
    __shared__ float red[16];

    const int tid  = threadIdx.x;    // 512
    const int row0 = blockIdx.x * 32;

    // --- stage X tile: 4096 float4-slots (4 rows each), coalesced LDG ---
    float lsum = 0.f;
#pragma unroll
    for (int it = 0; it < 8; it++) {
        int slot = tid + it * 512;       // < 4096
        int d  = slot & 511;
        int r4 = slot >> 9;              // row group 0..7
        int c  = d >> 5, s = d & 31;
        const float* xp = X + (size_t)(row0 + r4 * 4) * DDIM + d;
        float v0 = xp[0];
        float v1 = xp[DDIM];
        float v2 = xp[2 * DDIM];
        float v3 = xp[3 * DDIM];
        lsum += (v0 + v1) + (v2 + v3);
        *(float4*)(Xs + c * XCPAD + s * XSPAD + r4 * 4) =
            make_float4(v0, v1, v2, v3);
    }
    // --- stage protos transposed [s][c][k] ---
#pragma unroll
    for (int it = 0; it < 16; it++) {
        int i = tid + it * 512;          // < 8192
        int c = i >> 9, k = (i >> 5) & 15, s = i & 31;
        Pt[s * PTPAD + c * 16 + k] = protos[i];
    }
    __syncthreads();

    // --- main dot products: thread = (kg, c, rg) -> 4 rows x 4 ks ---
    const int kg = tid & 3;              // codeword group (4 ks)
    const int c  = (tid >> 2) & 15;      // codebook
    const int rg = tid >> 6;             // row group 0..7

    float pnl[4];
#pragma unroll
    for (int kk = 0; kk < 4; kk++) pnl[kk] = g_pn[c * 16 + kg * 4 + kk];

    float acc[4][4];
#pragma unroll
    for (int r = 0; r < 4; r++)
#pragma unroll
        for (int kk = 0; kk < 4; kk++) acc[r][kk] = 0.f;

    const float* xb = Xs + c * XCPAD + rg * 4;
    const float* pb = Pt + c * 16 + kg * 4;

#pragma unroll
    for (int s = 0; s < 32; s++) {
        const float4 xv = *(const float4*)(xb + s * XSPAD);
        const float4 pv = *(const float4*)(pb + s * PTPAD);
        acc[0][0] = fmaf(xv.x, pv.x, acc[0][0]);
        acc[0][1] = fmaf(xv.x, pv.y, acc[0][1]);
        acc[0][2] = fmaf(xv.x, pv.z, acc[0][2]);
        acc[0][3] = fmaf(xv.x, pv.w, acc[0][3]);
        acc[1][0] = fmaf(xv.y, pv.x, acc[1][0]);
        acc[1][1] = fmaf(xv.y, pv.y, acc[1][1]);
        acc[1][2] = fmaf(xv.y, pv.z, acc[1][2]);
        acc[1][3] = fmaf(xv.y, pv.w, acc[1][3]);
        acc[2][0] = fmaf(xv.z, pv.x, acc[2][0]);
        acc[2][1] = fmaf(xv.z, pv.y, acc[2][1]);
        acc[2][2] = fmaf(xv.z, pv.z, acc[2][2]);
        acc[2][3] = fmaf(xv.z, pv.w, acc[2][3]);
        acc[3][0] = fmaf(xv.w, pv.x, acc[3][0]);
        acc[3][1] = fmaf(xv.w, pv.y, acc[3][1]);
        acc[3][2] = fmaf(xv.w, pv.z, acc[3][2]);
        acc[3][3] = fmaf(xv.w, pv.w, acc[3][3]);
    }

    // --- argmin per (row, codebook): local then across 4 kg lanes ---
#pragma unroll
    for (int r = 0; r < 4; r++) {
        float bd = pnl[0] - 2.f * acc[r][0];
        int   bk = kg * 4;
#pragma unroll
        for (int kk = 1; kk < 4; kk++) {
            float dd = pnl[kk] - 2.f * acc[r][kk];
            if (dd < bd) { bd = dd; bk = kg * 4 + kk; }
        }
#pragma unroll
        for (int off = 1; off < 4; off <<= 1) {
            float od = __shfl_xor_sync(0xffffffffu, bd, off);
            int   ok = __shfl_xor_sync(0xffffffffu, bk, off);
            if (od < bd || (od == bd && ok < bk)) { bd = od; bk = ok; }
        }
        if (kg == 0)
            codes_s[(rg * 4 + r) * 16 + c] = (unsigned char)bk;
    }

    // --- deterministic block reduction of lsum (512 thr = 16 warps) ---
#pragma unroll
    for (int off = 16; off; off >>= 1)
        lsum += __shfl_xor_sync(0xffffffffu, lsum, off);
    if ((tid & 31) == 0) red[tid >> 5] = lsum;
    __syncthreads();                      // also publishes codes_s
    if (tid < 16) {
        float v = red[tid];
        v += __shfl_xor_sync(0xffffu, v, 1);
        v += __shfl_xor_sync(0xffffu, v, 2);
        v += __shfl_xor_sync(0xffffu, v, 4);
        v += __shfl_xor_sync(0xffffu, v, 8);
        if (tid == 0) g_bsums[blockIdx.x] = v;
    }

    // --- build paired codes: entry = p*256 + k1*16 + k2 (u16) ---
    if (tid < 256) {
        int r = tid >> 3, p = tid & 7;
        int k1 = codes_s[r * 16 + 2 * p];
        int k2 = codes_s[r * 16 + 2 * p + 1];
        g_pcodes[(row0 + r) * 8 + p] =
            (unsigned short)(p * 256 + k1 * 16 + k2);
    }
}

// ============================================================
// Kernel 2: reduce block sums -> g_scale = mean(X). 1 block.
// ============================================================
__global__ void reduce_kernel() {
    const int tid = threadIdx.x;         // 256 threads
    float s = 0.f;
    for (int i = tid; i < 1024; i += 256) s += g_bsums[i];
    __shared__ float red[8];
#pragma unroll
    for (int off = 16; off; off >>= 1)
        s += __shfl_xor_sync(0xffffffffu, s, off);
    if ((tid & 31) == 0) red[tid >> 5] = s;
    __syncthreads();
    if (tid < 8) {
        float v = red[tid];
        v += __shfl_xor_sync(0xffu, v, 1);
        v += __shfl_xor_sync(0xffu, v, 2);
        v += __shfl_xor_sync(0xffu, v, 4);
        if (tid == 0) g_scale = v * (1.0f / (float)(NROWS * DDIM));
    }
}

// ============================================================
// Kernel 3: paired-LUT accumulate, fp16 plut + HADD2 accumulate.
// Grid (32 m-tiles of 32 cols, 32 row chunks of 1024 rows),
// 1024 threads/block. Thread = 8 cols of one row (4 lanes/row).
// Per entry: 1 SHF/AND + 1 IMAD + 1 LDS.128 + 4 HADD2.
// Epilogue: one half->float conversion + fp32 scale.
// smem: stage fp32 (32KB) + plutH[8*256][32] fp16 (128KB).
// ============================================================
#define ACC_SMEM (256 * 32 * 4 + 8 * 256 * 32 * 2)

__global__ void accum_kernel(const float* __restrict__ luts,
                             float* __restrict__ out) {
    extern __shared__ float sm[];
    float*   stage = sm;                         // 256 * 32 floats
    __half*  plutH = (__half*)(sm + 256 * 32);   // 8*256*32 halfs

    const int tid = threadIdx.x;         // 1024
    const int m0  = blockIdx.x * 32;

    // --- stage lut slice [16c*16k][32m] fp32 (conflict-free float4) ---
#pragma unroll
    for (int it = 0; it < 2; it++) {
        int i = tid + it * 1024;         // < 2048  (256 rows * 8 float4)
        int rowck = i >> 3, q = i & 7;
        *(float4*)(stage + rowck * 32 + q * 4) =
            *(const float4*)(luts + rowck * MOUT + m0 + q * 4);
    }
    __syncthreads();

    // --- build pairwise fp16 LUT: 8*256 entries x 32 cols ---
#pragma unroll
    for (int it = 0; it < 16; it++) {
        int i     = tid + it * 1024;     // < 16384 (entry*8 + q)
        int q     = i & 7;               // float4 group within 32 cols
        int entry = i >> 3;              // p*256 + k12
        int k12   = entry & 255;
        int p     = entry >> 8;
        int k1    = k12 >> 4, k2 = k12 & 15;
        const float4 a = *(const float4*)(stage + ((2 * p) * 16 + k1) * 32 + q * 4);
        const float4 b = *(const float4*)(stage + ((2 * p + 1) * 16 + k2) * 32 + q * 4);
        __half2 h0 = __floats2half2_rn(a.x + b.x, a.y + b.y);
        __half2 h1 = __floats2half2_rn(a.z + b.z, a.w + b.w);
        uint2 pk2;
        pk2.x = *(uint32_t*)&h0;
        pk2.y = *(uint32_t*)&h1;
        *(uint2*)(plutH + (size_t)entry * 32 + q * 4) = pk2;
    }
    __syncthreads();

    const float scale = g_scale;
    const int mg = tid & 3;              // 8-col group within 32-col tile
    const int rl = tid >> 2;             // 256 rows in flight
    const int rowBase = blockIdx.y * 1024;
    const __half* lutBase = plutH + mg * 8;   // mg*16 bytes

#pragma unroll
    for (int rr = 0; rr < 4; rr++) {
        const int row = rowBase + rl + rr * 256;
        const uint4 cw = *(const uint4*)(g_pcodes + row * 8);
        const uint32_t w[4] = {cw.x, cw.y, cw.z, cw.w};

        __half2 a0 = __half2half2(__ushort_as_half(0));
        __half2 a1 = a0, a2 = a0, a3 = a0;
#pragma unroll
        for (int p = 0; p < 8; p++) {
            uint32_t ww = w[p >> 1];
            uint32_t e  = (p & 1) ? (ww >> 16) : (ww & 0xFFFFu);
            const uint4 v = *(const uint4*)(lutBase + (e << 5));
            a0 = __hadd2(a0, *(const __half2*)&v.x);
            a1 = __hadd2(a1, *(const __half2*)&v.y);
            a2 = __hadd2(a2, *(const __half2*)&v.z);
            a3 = __hadd2(a3, *(const __half2*)&v.w);
        }
        const float2 f0 = __half22float2(a0);
        const float2 f1 = __half22float2(a1);
        const float2 f2 = __half22float2(a2);
        const float2 f3 = __half22float2(a3);
        float* op = out + (size_t)row * MOUT + m0 + mg * 8;
        float4 o1, o2;
        o1.x = f0.x * scale; o1.y = f0.y * scale;
        o1.z = f1.x * scale; o1.w = f1.y * scale;
        o2.x = f2.x * scale; o2.y = f2.y * scale;
        o2.z = f3.x * scale; o2.w = f3.y * scale;
        *(float4*)op       = o1;
        *(float4*)(op + 4) = o2;
    }
}

// ============================================================
extern "C" void kernel_launch(void* const* d_in, const int* in_sizes, int n_in,
                              void* d_out, int out_size) {
    const float* X      = (const float*)d_in[0];   // [32768, 512]
    const float* protos = (const float*)d_in[1];   // [16, 16, 32]
    const float* luts   = (const float*)d_in[2];   // [16, 16, 1024]
    float* out = (float*)d_out;                    // [32768, 1024]

    cudaFuncSetAttribute(encode_kernel,
        cudaFuncAttributeMaxDynamicSharedMemorySize, ENC_SMEM);
    cudaFuncSetAttribute(accum_kernel,
        cudaFuncAttributeMaxDynamicSharedMemorySize, ACC_SMEM);

    prep_pnorm<<<1, 256>>>(protos);
    encode_kernel<<<NROWS / 32, 512, ENC_SMEM>>>(X, protos);
    reduce_kernel<<<1, 256>>>();
    accum_kernel<<<dim3(32, 32), 1024, ACC_SMEM>>>(luts, out);
}

// round 7
// speedup vs baseline: 1.9501x; 1.0140x over previous
#include <cuda_runtime.h>
#include <cuda_fp16.h>
#include <cstdint>

// Problem constants
#define NROWS 32768
#define DDIM  512
#define CB    16     // codebooks
#define KC    16     // codewords per codebook
#define SV    32     // subvector length
#define MOUT  1024

// ---- device scratch (no allocations allowed) ----
__device__ float          g_pn[CB * KC];            // ||proto||^2
__device__ float          g_bsums[1024];            // per-block X sums
__device__ float          g_scale;                  // mean(X)
__device__ unsigned short g_pcodes[NROWS * 8];      // paired codes: p*256+k1*16+k2
__device__ __half         g_plut[8 * 256 * MOUT];   // global paired LUT (4MB, fp16)

// ============================================================
// Kernel 0: prototype squared norms. 1 block x 256 threads.
// ============================================================
__global__ void prep_pnorm(const float* __restrict__ protos) {
    int t = threadIdx.x;                 // t = c*16 + k
    const float* p = protos + t * SV;
    float s = 0.f;
#pragma unroll
    for (int i = 0; i < SV; i++) s += p[i] * p[i];
    g_pn[t] = s;
}

// ============================================================
// Kernel 0b: build global paired fp16 LUT once.
// plut[p*256 + k1*16 + k2][m] = rn_fp16( lut[2p][k1][m] + lut[2p+1][k2][m] )
// Grid 2048 blocks (one per entry) x 512 threads (2 cols each).
// Values bit-identical to the old per-block smem build.
// ============================================================
__global__ void build_plut(const float* __restrict__ luts) {
    const int entry = blockIdx.x;        // p*256 + k12
    const int k12 = entry & 255, p = entry >> 8;
    const int k1 = k12 >> 4, k2 = k12 & 15;
    const int col = threadIdx.x * 2;
    const float2 a = *(const float2*)(luts + ((2 * p) * 16 + k1) * MOUT + col);
    const float2 b = *(const float2*)(luts + ((2 * p + 1) * 16 + k2) * MOUT + col);
    __half2 h = __floats2half2_rn(a.x + b.x, a.y + b.y);
    *(__half2*)(g_plut + (size_t)entry * MOUT + col) = h;
}

// ============================================================
// Kernel 1: encode. Block = 512 threads, 32 rows per block.
// NUMERICS UNCHANGED from the passing version (argmin must be
// bit-stable). Only launch_bounds added for 2 blocks/SM.
// ============================================================
#define XCPAD 1156
#define XSPAD 36
#define PTPAD 260
#define ENC_SMEM ((16 * XCPAD + 32 * PTPAD) * 4)

__global__ void __launch_bounds__(512, 2)
encode_kernel(const float* __restrict__ X,
              const float* __restrict__ protos) {
    extern __shared__ float sm[];
    float* Xs = sm;                  // 16 * 1156
    float* Pt = sm + 16 * XCPAD;     // 32 * 260

    __shared__ unsigned char codes_s[32 * 16];
    __shared__ float red[16];

    const int tid  = threadIdx.x;    // 512
    const int row0 = blockIdx.x * 32;

    // --- stage X tile: 4096 float4-slots (4 rows each), coalesced LDG ---
    float lsum = 0.f;
#pragma unroll
    for (int it = 0; it < 8; it++) {
        int slot = tid + it * 512;       // < 4096
        int d  = slot & 511;
        int r4 = slot >> 9;              // row group 0..7
        int c  = d >> 5, s = d & 31;
        const float* xp = X + (size_t)(row0 + r4 * 4) * DDIM + d;
        float v0 = xp[0];
        float v1 = xp[DDIM];
        float v2 = xp[2 * DDIM];
        float v3 = xp[3 * DDIM];
        lsum += (v0 + v1) + (v2 + v3);
        *(float4*)(Xs + c * XCPAD + s * XSPAD + r4 * 4) =
            make_float4(v0, v1, v2, v3);
    }
    // --- stage protos transposed [s][c][k] ---
#pragma unroll
    for (int it = 0; it < 16; it++) {
        int i = tid + it * 512;          // < 8192
        int c = i >> 9, k = (i >> 5) & 15, s = i & 31;
        Pt[s * PTPAD + c * 16 + k] = protos[i];
    }
    __syncthreads();

    // --- main dot products: thread = (kg, c, rg) -> 4 rows x 4 ks ---
    const int kg = tid & 3;              // codeword group (4 ks)
    const int c  = (tid >> 2) & 15;      // codebook
    const int rg = tid >> 6;             // row group 0..7

    float pnl[4];
#pragma unroll
    for (int kk = 0; kk < 4; kk++) pnl[kk] = g_pn[c * 16 + kg * 4 + kk];

    float acc[4][4];
#pragma unroll
    for (int r = 0; r < 4; r++)
#pragma unroll
        for (int kk = 0; kk < 4; kk++) acc[r][kk] = 0.f;

    const float* xb = Xs + c * XCPAD + rg * 4;
    const float* pb = Pt + c * 16 + kg * 4;

#pragma unroll
    for (int s = 0; s < 32; s++) {
        const float4 xv = *(const float4*)(xb + s * XSPAD);
        const float4 pv = *(const float4*)(pb + s * PTPAD);
        acc[0][0] = fmaf(xv.x, pv.x, acc[0][0]);
        acc[0][1] = fmaf(xv.x, pv.y, acc[0][1]);
        acc[0][2] = fmaf(xv.x, pv.z, acc[0][2]);
        acc[0][3] = fmaf(xv.x, pv.w, acc[0][3]);
        acc[1][0] = fmaf(xv.y, pv.x, acc[1][0]);
        acc[1][1] = fmaf(xv.y, pv.y, acc[1][1]);
        acc[1][2] = fmaf(xv.y, pv.z, acc[1][2]);
        acc[1][3] = fmaf(xv.y, pv.w, acc[1][3]);
        acc[2][0] = fmaf(xv.z, pv.x, acc[2][0]);
        acc[2][1] = fmaf(xv.z, pv.y, acc[2][1]);
        acc[2][2] = fmaf(xv.z, pv.z, acc[2][2]);
        acc[2][3] = fmaf(xv.z, pv.w, acc[2][3]);
        acc[3][0] = fmaf(xv.w, pv.x, acc[3][0]);
        acc[3][1] = fmaf(xv.w, pv.y, acc[3][1]);
        acc[3][2] = fmaf(xv.w, pv.z, acc[3][2]);
        acc[3][3] = fmaf(xv.w, pv.w, acc[3][3]);
    }

    // --- argmin per (row, codebook): local then across 4 kg lanes ---
#pragma unroll
    for (int r = 0; r < 4; r++) {
        float bd = pnl[0] - 2.f * acc[r][0];
        int   bk = kg * 4;
#pragma unroll
        for (int kk = 1; kk < 4; kk++) {
            float dd = pnl[kk] - 2.f * acc[r][kk];
            if (dd < bd) { bd = dd; bk = kg * 4 + kk; }
        }
#pragma unroll
        for (int off = 1; off < 4; off <<= 1) {
            float od = __shfl_xor_sync(0xffffffffu, bd, off);
            int   ok = __shfl_xor_sync(0xffffffffu, bk, off);
            if (od < bd || (od == bd && ok < bk)) { bd = od; bk = ok; }
        }
        if (kg == 0)
            codes_s[(rg * 4 + r) * 16 + c] = (unsigned char)bk;
    }

    // --- deterministic block reduction of lsum (512 thr = 16 warps) ---
#pragma unroll
    for (int off = 16; off; off >>= 1)
        lsum += __shfl_xor_sync(0xffffffffu, lsum, off);
    if ((tid & 31) == 0) red[tid >> 5] = lsum;
    __syncthreads();                      // also publishes codes_s
    if (tid < 16) {
        float v = red[tid];
        v += __shfl_xor_sync(0xffffu, v, 1);
        v += __shfl_xor_sync(0xffffu, v, 2);
        v += __shfl_xor_sync(0xffffu, v, 4);
        v += __shfl_xor_sync(0xffffu, v, 8);
        if (tid == 0) g_bsums[blockIdx.x] = v;
    }

    // --- build paired codes: entry = p*256 + k1*16 + k2 (u16) ---
    if (tid < 256) {
        int r = tid >> 3, p = tid & 7;
        int k1 = codes_s[r * 16 + 2 * p];
        int k2 = codes_s[r * 16 + 2 * p + 1];
        g_pcodes[(row0 + r) * 8 + p] =
            (unsigned short)(p * 256 + k1 * 16 + k2);
    }
}

// ============================================================
// Kernel 2: reduce block sums -> g_scale = mean(X). 1 block.
// ============================================================
__global__ void reduce_kernel() {
    const int tid = threadIdx.x;         // 256 threads
    float s = 0.f;
    for (int i = tid; i < 1024; i += 256) s += g_bsums[i];
    __shared__ float red[8];
#pragma unroll
    for (int off = 16; off; off >>= 1)
        s += __shfl_xor_sync(0xffffffffu, s, off);
    if ((tid & 31) == 0) red[tid >> 5] = s;
    __syncthreads();
    if (tid < 8) {
        float v = red[tid];
        v += __shfl_xor_sync(0xffu, v, 1);
        v += __shfl_xor_sync(0xffu, v, 2);
        v += __shfl_xor_sync(0xffu, v, 4);
        if (tid == 0) g_scale = v * (1.0f / (float)(NROWS * DDIM));
    }
}

// ============================================================
// Kernel 3: paired-LUT accumulate.
// Block copies its 128KB fp16 plut slice from the precomputed
// global table (L2-resident, strided LDG -> STS), then runs the
// HADD2 gather loop. Per-block build traffic drops from ~5.1K
// L1 wavefronts to ~2K (copy only).
// Grid (32 m-tiles of 32 cols, 32 row chunks of 1024 rows),
// 1024 threads/block. Codes prefetched 4-deep (MLP=4).
// ============================================================
#define ACC_SMEM (8 * 256 * 32 * 2)      // 128KB

__global__ void accum_kernel(float* __restrict__ out) {
    extern __shared__ __half plutH[];    // [2048 entries][32 cols]

    const int tid = threadIdx.x;         // 1024
    const int m0  = blockIdx.x * 32;

    // --- copy plut slice: 2048 entries x 64B, strided from gmem ---
#pragma unroll
    for (int it = 0; it < 8; it++) {
        int i = tid + it * 1024;         // < 8192
        int e = i >> 2, g = i & 3;       // entry, 16B group
        *(uint4*)(plutH + e * 32 + g * 8) =
            *(const uint4*)(g_plut + (size_t)e * MOUT + m0 + g * 8);
    }
    __syncthreads();

    const float scale = g_scale;
    const int mg = tid & 3;              // 8-col group within 32-col tile
    const int rl = tid >> 2;             // 256 rows in flight
    const int rowBase = blockIdx.y * 1024 + rl;
    const __half* lutBase = plutH + mg * 8;   // mg*16 bytes

    // --- prefetch all 4 rows' pair-codes (MLP=4) ---
    uint4 cw4[4];
#pragma unroll
    for (int rr = 0; rr < 4; rr++)
        cw4[rr] = *(const uint4*)(g_pcodes + (size_t)(rowBase + rr * 256) * 8);

#pragma unroll
    for (int rr = 0; rr < 4; rr++) {
        const int row = rowBase + rr * 256;
        const uint32_t w[4] = {cw4[rr].x, cw4[rr].y, cw4[rr].z, cw4[rr].w};

        __half2 a0 = __half2half2(__ushort_as_half(0));
        __half2 a1 = a0, a2 = a0, a3 = a0;
#pragma unroll
        for (int p = 0; p < 8; p++) {
            uint32_t ww = w[p >> 1];
            uint32_t e  = (p & 1) ? (ww >> 16) : (ww & 0xFFFFu);
            const uint4 v = *(const uint4*)(lutBase + (e << 5));
            a0 = __hadd2(a0, *(const __half2*)&v.x);
            a1 = __hadd2(a1, *(const __half2*)&v.y);
            a2 = __hadd2(a2, *(const __half2*)&v.z);
            a3 = __hadd2(a3, *(const __half2*)&v.w);
        }
        const float2 f0 = __half22float2(a0);
        const float2 f1 = __half22float2(a1);
        const float2 f2 = __half22float2(a2);
        const float2 f3 = __half22float2(a3);
        float* op = out + (size_t)row * MOUT + m0 + mg * 8;
        float4 o1, o2;
        o1.x = f0.x * scale; o1.y = f0.y * scale;
        o1.z = f1.x * scale; o1.w = f1.y * scale;
        o2.x = f2.x * scale; o2.y = f2.y * scale;
        o2.z = f3.x * scale; o2.w = f3.y * scale;
        *(float4*)op       = o1;
        *(float4*)(op + 4) = o2;
    }
}

// ============================================================
extern "C" void kernel_launch(void* const* d_in, const int* in_sizes, int n_in,
                              void* d_out, int out_size) {
    const float* X      = (const float*)d_in[0];   // [32768, 512]
    const float* protos = (const float*)d_in[1];   // [16, 16, 32]
    const float* luts   = (const float*)d_in[2];   // [16, 16, 1024]
    float* out = (float*)d_out;                    // [32768, 1024]

    cudaFuncSetAttribute(encode_kernel,
        cudaFuncAttributeMaxDynamicSharedMemorySize, ENC_SMEM);
    cudaFuncSetAttribute(accum_kernel,
        cudaFuncAttributeMaxDynamicSharedMemorySize, ACC_SMEM);

    prep_pnorm<<<1, 256>>>(protos);
    build_plut<<<2048, 512>>>(luts);
    encode_kernel<<<NROWS / 32, 512, ENC_SMEM>>>(X, protos);
    reduce_kernel<<<1, 256>>>();
    accum_kernel<<<dim3(32, 32), 1024, ACC_SMEM>>>(out);
}